// round 4
// baseline (speedup 1.0000x reference)
#include <cuda_runtime.h>
#include <stdint.h>
#include <math.h>

#define MAXB 64
#define TPB 256

struct Meta {
    unsigned prefix[MAXB + 1]; // prefix of H*s_i^2 in output elements
    unsigned s[MAXB];
    unsigned s2[MAXB];
    unsigned ms[MAXB];   // magic multiplier for divide-by-s
    unsigned shs[MAXB];  // shift for divide-by-s
    unsigned ms2[MAXB];  // magic multiplier for divide-by-s2
    unsigned shs2[MAXB]; // shift for divide-by-s2
};

__device__ Meta g_meta;

// Granlund-Montgomery round-up magic: q = (x*m) >> sh == x/d, valid for
// x < 2^31, d >= 2. Proof sketch: m = (2^p + e)/d with p = 31+k, e < 2^k,
// error term e*x < 2^p, so floor is exact.
__device__ __forceinline__ void magic_u32(unsigned d, unsigned& m, unsigned& sh) {
    unsigned k = 32u - __clz(d - 1u);          // ceil(log2 d), d >= 2
    unsigned long long two = 1ull << (31 + k);
    m = (unsigned)((two + d - 1ull) / d);      // ceil(2^(31+k)/d), fits u32
    sh = 31u + k;
}

__global__ void setup_kernel(const int* __restrict__ seq, const int* __restrict__ nh, int B) {
    if (threadIdx.x != 0 || blockIdx.x != 0) return;
    unsigned H = nh ? (unsigned)(*nh) : 16u;
    unsigned acc = 0;
    for (int i = 0; i < B; ++i) {
        unsigned s = (unsigned)seq[i];
        unsigned s2 = s * s;
        g_meta.prefix[i] = acc;
        g_meta.s[i] = s;
        g_meta.s2[i] = s2;
        magic_u32(s, g_meta.ms[i], g_meta.shs[i]);
        magic_u32(s2, g_meta.ms2[i], g_meta.shs2[i]);
        acc += H * s2;
    }
    g_meta.prefix[B] = acc;
}

__global__ void __launch_bounds__(TPB)
pack_kernel(const float* __restrict__ mask, float* __restrict__ out,
            unsigned out_size, unsigned nvec, int B, unsigned S) {
    __shared__ unsigned sh_prefix[MAXB + 1];
    __shared__ unsigned sh_s[MAXB], sh_s2[MAXB];
    __shared__ unsigned sh_ms[MAXB], sh_shs[MAXB], sh_ms2[MAXB], sh_shs2[MAXB];

    for (int t = threadIdx.x; t <= B; t += TPB) sh_prefix[t] = g_meta.prefix[t];
    for (int t = threadIdx.x; t < B; t += TPB) {
        sh_s[t] = g_meta.s[t];     sh_s2[t] = g_meta.s2[t];
        sh_ms[t] = g_meta.ms[t];   sh_shs[t] = g_meta.shs[t];
        sh_ms2[t] = g_meta.ms2[t]; sh_shs2[t] = g_meta.shs2[t];
    }
    __syncthreads();

    unsigned v = blockIdx.x * TPB + threadIdx.x;
    if (v >= nvec) return;
    unsigned base = v * 4u; // 4 floats = 16 bytes per thread

    // find batch i: prefix[i] <= base < prefix[i+1]. Piece lengths are
    // multiples of 16 (H=16 * s^2), so a 4-elem vector never straddles one.
    int i = 0;
    while (i + 1 < B && base >= sh_prefix[i + 1]) ++i;

    unsigned rem = base - sh_prefix[i];
    unsigned s  = sh_s[i];
    unsigned s2 = sh_s2[i];
    unsigned h  = (unsigned)(((unsigned long long)rem * sh_ms2[i]) >> sh_shs2[i]);
    unsigned pos = rem - h * s2;                                        // pos in [0, s2)
    unsigned r = (unsigned)(((unsigned long long)pos * sh_ms[i]) >> sh_shs[i]);
    unsigned c = pos - r * s;

    if (base + 4u <= out_size && c + 4u <= s) {
        // fast path: 4 floats inside one source row
        const float* src = mask + ((size_t)i * S + r) * (size_t)S + c;
        float4 R;
        R.x = __ldg(src + 0);
        R.y = __ldg(src + 1);
        R.z = __ldg(src + 2);
        R.w = __ldg(src + 3);
        *reinterpret_cast<float4*>(out + base) = R; // base*4B is 16B-aligned
    } else {
        // slow path: row wrap / tail — scalar per element
        for (unsigned j = 0; j < 4u; ++j) {
            unsigned idx = base + j;
            if (idx >= out_size) break;
            unsigned rem2 = idx - sh_prefix[i];
            unsigned hh  = (unsigned)(((unsigned long long)rem2 * sh_ms2[i]) >> sh_shs2[i]);
            unsigned p2  = rem2 - hh * s2;
            unsigned rr  = (unsigned)(((unsigned long long)p2 * sh_ms[i]) >> sh_shs[i]);
            unsigned cc  = p2 - rr * s;
            out[idx] = mask[((size_t)i * S + rr) * (size_t)S + cc];
        }
    }
}

extern "C" void kernel_launch(void* const* d_in, const int* in_sizes, int n_in,
                              void* d_out, int out_size) {
    const float* mask = (const float*)d_in[0];
    const int* seq = (const int*)d_in[1];
    const int* nh = (n_in >= 3) ? (const int*)d_in[2] : nullptr;

    int B = in_sizes[1];
    if (B > MAXB) B = MAXB;
    long long SS = (long long)in_sizes[0] / (B > 0 ? B : 1);
    unsigned S = (unsigned)(sqrt((double)SS) + 0.5);

    setup_kernel<<<1, 32>>>(seq, nh, B);

    unsigned osz = (unsigned)out_size;
    unsigned nvec = (osz + 3u) / 4u;
    if (nvec == 0) return;
    unsigned grid = (nvec + TPB - 1) / TPB;
    pack_kernel<<<grid, TPB>>>(mask, (float*)d_out, osz, nvec, B, S);
}